// round 6
// baseline (speedup 1.0000x reference)
#include <cuda_runtime.h>
#include <math.h>

#define B_   32
#define S_   1024
#define DM   48
#define NH   3
#define DK   16
#define BH_  (B_*NH)            // 96
#define H_ELEMS (B_*S_*DM)      // 1572864

typedef unsigned long long ull;

// Scratch (no allocations allowed)
__device__ float g_Q[BH_*S_*DK];
__device__ float g_K[BH_*S_*DK];
__device__ float g_V[BH_*S_*DK];
__device__ float g_Hcat[B_*S_*DM];

union F4U { float4 f4; ull u2[2]; float f[4]; };

// ---------------------------------------------------------------------------
// Linear core: Y = X @ W^T + b for a 128-row slab. 384 threads. (unchanged)
// ---------------------------------------------------------------------------
__device__ __forceinline__ void lin_core(const float* __restrict__ X,
    const float* __restrict__ W, const float* __restrict__ bias,
    int row0, float scale, float* __restrict__ out, int headsplit)
{
    __shared__ float Ws[48*49];
    __shared__ float bs[48];
    __shared__ float Xs[128*48];
    int tid = threadIdx.x;
    for (int i = tid; i < 48*48; i += 384) Ws[(i/48)*49 + (i%48)] = W[i];
    if (tid < 48) bs[tid] = bias[tid];
    const float4* Xg4 = (const float4*)(X + row0*48);
    float4* Xs4 = (float4*)Xs;
    for (int i = tid; i < 1536; i += 384) Xs4[i] = Xg4[i];
    __syncthreads();

    int r0 = tid / 12, jg = tid % 12;
    float acc[4][4];
#pragma unroll
    for (int rr = 0; rr < 4; rr++)
#pragma unroll
        for (int jj = 0; jj < 4; jj++) acc[rr][jj] = bs[jg*4 + jj];

#pragma unroll 4
    for (int c = 0; c < 48; c++) {
        float xv[4], wv[4];
#pragma unroll
        for (int rr = 0; rr < 4; rr++) xv[rr] = Xs[(r0 + 32*rr)*48 + c];
#pragma unroll
        for (int jj = 0; jj < 4; jj++) wv[jj] = Ws[(jg*4 + jj)*49 + c];
#pragma unroll
        for (int rr = 0; rr < 4; rr++)
#pragma unroll
            for (int jj = 0; jj < 4; jj++)
                acc[rr][jj] = fmaf(xv[rr], wv[jj], acc[rr][jj]);
    }

    int j0 = jg * 4;
#pragma unroll
    for (int rr = 0; rr < 4; rr++) {
        int grow = row0 + r0 + 32*rr;
        float4 v = make_float4(acc[rr][0]*scale, acc[rr][1]*scale,
                               acc[rr][2]*scale, acc[rr][3]*scale);
        if (headsplit) {
            int b = grow >> 10, s = grow & 1023;
            int h = j0 >> 4,  d = j0 & 15;
            *(float4*)(out + ((b*NH + h)*S_ + s)*DK + d) = v;
        } else {
            *(float4*)(out + grow*48 + j0) = v;
        }
    }
}

__global__ __launch_bounds__(384) void qkv48(
    const float* __restrict__ Xq, const float* __restrict__ Wq, const float* __restrict__ bq,
    const float* __restrict__ Xk, const float* __restrict__ Wk, const float* __restrict__ bk,
    const float* __restrict__ Xv, const float* __restrict__ Wv, const float* __restrict__ bv)
{
    int m = blockIdx.y;
    const float *X, *W, *bb; float* dst; float scale;
    // Q scale folds 1/sqrt(dk) AND log2(e): attention uses ex2 directly.
    if (m == 0)      { X = Xq; W = Wq; bb = bq; dst = g_Q; scale = 0.25f * 1.4426950408889634f; }
    else if (m == 1) { X = Xk; W = Wk; bb = bk; dst = g_K; scale = 1.0f; }
    else             { X = Xv; W = Wv; bb = bv; dst = g_V; scale = 1.0f; }
    lin_core(X, W, bb, blockIdx.x * 128, scale, dst, 1);
}

__global__ __launch_bounds__(384) void proj48(
    const float* __restrict__ Wh, const float* __restrict__ bhp, float* __restrict__ out)
{
    lin_core((const float*)g_Hcat, Wh, bhp, blockIdx.x * 128, 1.0f, out, 0);
}

// ---------------------------------------------------------------------------
// Attention, E-resident design.
// Block = (q-tile of 32 rows, bh). 512 threads = 16 warps. lane = q-row,
// warp w owns k-slice [w*64, w*64+64).
// smem: KV buffer (K for pass1, V for pass2), E tile 32 x 1024 fp32
// (row stride 1026 floats -> conflict-free float2 ops), lsum, inv.
// P1: e = ex2(q.k) -> E smem + row sums (exp computed ONCE).
// P2a: A = E * inv, coalesced float2 stores.
// P2b: AV from E smem (no recompute), slab-reduce 16 warps -> Hcat.
// ---------------------------------------------------------------------------
#define EP      1026                 // E row pad (floats): 513 float2, odd f2 stride
#define KV_F    16384                // 1024*16 floats
#define ES_F    (32*EP)              // 32832
#define SM_FLOATS (KV_F + ES_F + 512 + 32)   // 49760 floats = 199040 B

__device__ __forceinline__ float dot_e(const F4U* __restrict__ qu,
                                       const float4* __restrict__ kr)
{
    F4U k0, k1, k2, k3;
    k0.f4 = kr[0]; k1.f4 = kr[1]; k2.f4 = kr[2]; k3.f4 = kr[3];
    ull a, b;
    asm("mul.rn.f32x2 %0,%1,%2;"    : "=l"(a) : "l"(qu[0].u2[0]), "l"(k0.u2[0]));
    asm("fma.rn.f32x2 %0,%1,%2,%0;" : "+l"(a) : "l"(qu[0].u2[1]), "l"(k0.u2[1]));
    asm("fma.rn.f32x2 %0,%1,%2,%0;" : "+l"(a) : "l"(qu[1].u2[0]), "l"(k1.u2[0]));
    asm("fma.rn.f32x2 %0,%1,%2,%0;" : "+l"(a) : "l"(qu[1].u2[1]), "l"(k1.u2[1]));
    asm("mul.rn.f32x2 %0,%1,%2;"    : "=l"(b) : "l"(qu[2].u2[0]), "l"(k2.u2[0]));
    asm("fma.rn.f32x2 %0,%1,%2,%0;" : "+l"(b) : "l"(qu[2].u2[1]), "l"(k2.u2[1]));
    asm("fma.rn.f32x2 %0,%1,%2,%0;" : "+l"(b) : "l"(qu[3].u2[0]), "l"(k3.u2[0]));
    asm("fma.rn.f32x2 %0,%1,%2,%0;" : "+l"(b) : "l"(qu[3].u2[1]), "l"(k3.u2[1]));
    asm("add.rn.f32x2 %0,%0,%1;"    : "+l"(a) : "l"(b));
    float lo, hi;
    asm("mov.b64 {%0,%1},%2;" : "=f"(lo), "=f"(hi) : "l"(a));
    float s = lo + hi;
    float r;
    asm("ex2.approx.f32 %0,%1;" : "=f"(r) : "f"(s));
    return r;
}

__global__ __launch_bounds__(512, 1) void attn_kernel(float* __restrict__ Aout)
{
    extern __shared__ float sm[];
    float4* KV4  = (float4*)sm;            // 4096 float4: K in P1, V in P2
    float*  Es   = sm + KV_F;
    float2* Es2  = (float2*)Es;            // row stride 513 float2
    float*  lsm  = sm + KV_F + ES_F;       // 16 x 32
    float*  invs = lsm + 512;              // 32

    int qt = blockIdx.x, bh = blockIdx.y;
    int tid = threadIdx.x, warp = tid >> 5, lane = tid & 31;
    int q0 = qt * 32;
    int kb = warp * 64;

    const float4* Kg = (const float4*)(g_K + bh*(S_*DK));
    const float4* Vg = (const float4*)(g_V + bh*(S_*DK));
    for (int i = tid; i < 4096; i += 512) KV4[i] = Kg[i];

    F4U qu[4];
    {
        const float4* qg = (const float4*)(g_Q + (bh*S_ + q0 + lane)*DK);
        qu[0].f4 = qg[0]; qu[1].f4 = qg[1]; qu[2].f4 = qg[2]; qu[3].f4 = qg[3];
    }
    __syncthreads();

    // ---- pass 1: exp once -> E smem + row sums ----
    float ls0 = 0.f, ls1 = 0.f;
#pragma unroll 2
    for (int kk = 0; kk < 64; kk += 2) {
        float e0 = dot_e(qu, KV4 + (kb + kk)*4);
        float e1 = dot_e(qu, KV4 + (kb + kk + 1)*4);
        Es2[lane*513 + ((kb + kk) >> 1)] = make_float2(e0, e1);
        ls0 += e0; ls1 += e1;
    }
    lsm[warp*32 + lane] = ls0 + ls1;
    __syncthreads();

    // V overwrites K; thread 0..31 computes row inverses meanwhile
    for (int i = tid; i < 4096; i += 512) KV4[i] = Vg[i];
    if (tid < 32) {
        float s = 0.f;
#pragma unroll
        for (int w = 0; w < 16; w++) s += lsm[w*32 + tid];
        invs[tid] = 1.0f / s;
    }
    __syncthreads();

    // ---- pass 2a: normalized A, coalesced float2 stores ----
    {
        int c2 = (kb >> 1) + lane;
        float* Ab = Aout + (bh*S_ + q0)*S_ + kb + lane*2;
#pragma unroll 4
        for (int r = 0; r < 32; r++) {
            float iv = invs[r];
            float2 e2 = Es2[r*513 + c2];
            e2.x *= iv; e2.y *= iv;
            *(float2*)(Ab + r*S_) = e2;
        }
    }

    // ---- pass 2b: AV from E smem ----
    ull acc[8];
#pragma unroll
    for (int j = 0; j < 8; j++) acc[j] = 0ULL;

#pragma unroll 2
    for (int kk = 0; kk < 64; kk += 2) {
        float2 e2 = Es2[lane*513 + ((kb + kk) >> 1)];
        ull ee0, ee1;
        asm("mov.b64 %0,{%1,%1};" : "=l"(ee0) : "f"(e2.x));
        asm("mov.b64 %0,{%1,%1};" : "=l"(ee1) : "f"(e2.y));
        F4U v0, v1, v2, v3;
        const float4* vp = KV4 + (kb + kk)*4;
        v0.f4 = vp[0]; v1.f4 = vp[1]; v2.f4 = vp[2]; v3.f4 = vp[3];
        asm("fma.rn.f32x2 %0,%1,%2,%0;" : "+l"(acc[0]) : "l"(ee0), "l"(v0.u2[0]));
        asm("fma.rn.f32x2 %0,%1,%2,%0;" : "+l"(acc[1]) : "l"(ee0), "l"(v0.u2[1]));
        asm("fma.rn.f32x2 %0,%1,%2,%0;" : "+l"(acc[2]) : "l"(ee0), "l"(v1.u2[0]));
        asm("fma.rn.f32x2 %0,%1,%2,%0;" : "+l"(acc[3]) : "l"(ee0), "l"(v1.u2[1]));
        F4U w0, w1, w2, w3;
        w0.f4 = vp[4]; w1.f4 = vp[5]; w2.f4 = vp[6]; w3.f4 = vp[7];
        asm("fma.rn.f32x2 %0,%1,%2,%0;" : "+l"(acc[4]) : "l"(ee0), "l"(v2.u2[0]));
        asm("fma.rn.f32x2 %0,%1,%2,%0;" : "+l"(acc[5]) : "l"(ee0), "l"(v2.u2[1]));
        asm("fma.rn.f32x2 %0,%1,%2,%0;" : "+l"(acc[6]) : "l"(ee0), "l"(v3.u2[0]));
        asm("fma.rn.f32x2 %0,%1,%2,%0;" : "+l"(acc[7]) : "l"(ee0), "l"(v3.u2[1]));
        asm("fma.rn.f32x2 %0,%1,%2,%0;" : "+l"(acc[0]) : "l"(ee1), "l"(w0.u2[0]));
        asm("fma.rn.f32x2 %0,%1,%2,%0;" : "+l"(acc[1]) : "l"(ee1), "l"(w0.u2[1]));
        asm("fma.rn.f32x2 %0,%1,%2,%0;" : "+l"(acc[2]) : "l"(ee1), "l"(w1.u2[0]));
        asm("fma.rn.f32x2 %0,%1,%2,%0;" : "+l"(acc[3]) : "l"(ee1), "l"(w1.u2[1]));
        asm("fma.rn.f32x2 %0,%1,%2,%0;" : "+l"(acc[4]) : "l"(ee1), "l"(w2.u2[0]));
        asm("fma.rn.f32x2 %0,%1,%2,%0;" : "+l"(acc[5]) : "l"(ee1), "l"(w2.u2[1]));
        asm("fma.rn.f32x2 %0,%1,%2,%0;" : "+l"(acc[6]) : "l"(ee1), "l"(w3.u2[0]));
        asm("fma.rn.f32x2 %0,%1,%2,%0;" : "+l"(acc[7]) : "l"(ee1), "l"(w3.u2[1]));
    }

    // scale by this row's inverse, stage slab, reduce across 16 warps
    float facc[16];
#pragma unroll
    for (int j = 0; j < 8; j++)
        asm("mov.b64 {%0,%1},%2;" : "=f"(facc[2*j]), "=f"(facc[2*j+1]) : "l"(acc[j]));
    float ivl = invs[lane];
#pragma unroll
    for (int j = 0; j < 16; j++) facc[j] *= ivl;

    __syncthreads();            // all V reads + A reads of Es complete
    {
        float4* sl4 = (float4*)(sm + (warp*32 + lane)*20);  // reuse KV area, pad 20
        sl4[0] = make_float4(facc[0],  facc[1],  facc[2],  facc[3]);
        sl4[1] = make_float4(facc[4],  facc[5],  facc[6],  facc[7]);
        sl4[2] = make_float4(facc[8],  facc[9],  facc[10], facc[11]);
        sl4[3] = make_float4(facc[12], facc[13], facc[14], facc[15]);
    }
    __syncthreads();
    {
        int row = tid >> 4, d = tid & 15;   // 512 threads = 32 rows x 16 dims
        float s = 0.f;
#pragma unroll
        for (int w = 0; w < 16; w++) s += sm[(w*32 + row)*20 + d];
        int b = bh / NH, h = bh - b*NH;
        g_Hcat[(b*S_ + q0 + row)*DM + h*DK + d] = s;
    }
}

// ---------------------------------------------------------------------------
extern "C" void kernel_launch(void* const* d_in, const int* in_sizes, int n_in,
                              void* d_out, int out_size)
{
    const float* Xq = (const float*)d_in[0];
    const float* Xk = (const float*)d_in[1];
    const float* Xv = (const float*)d_in[2];
    const float* Wq = (const float*)d_in[3];
    const float* bq = (const float*)d_in[4];
    const float* Wk = (const float*)d_in[5];
    const float* bk = (const float*)d_in[6];
    const float* Wv = (const float*)d_in[7];
    const float* bv = (const float*)d_in[8];
    const float* Wh = (const float*)d_in[9];
    const float* bh = (const float*)d_in[10];

    float* outH = (float*)d_out;
    float* outA = (float*)d_out + H_ELEMS;

    const int smem_bytes = SM_FLOATS * 4;   // 199040 B
    cudaFuncSetAttribute(attn_kernel, cudaFuncAttributeMaxDynamicSharedMemorySize, smem_bytes);

    qkv48<<<dim3(256, 3), 384>>>(Xq, Wq, bq, Xk, Wk, bk, Xv, Wv, bv);
    attn_kernel<<<dim3(32, BH_), 512, smem_bytes>>>(outA);
    proj48<<<256, 384>>>(Wh, bh, outH);
}

// round 7
// speedup vs baseline: 1.0474x; 1.0474x over previous
#include <cuda_runtime.h>
#include <math.h>

#define B_   32
#define S_   1024
#define DM   48
#define NH   3
#define DK   16
#define BH_  (B_*NH)            // 96
#define H_ELEMS (B_*S_*DM)      // 1572864

typedef unsigned long long ull;

// Scratch (no allocations allowed)
__device__ float g_Q[BH_*S_*DK];
__device__ float g_K[BH_*S_*DK];
__device__ float g_V[BH_*S_*DK];
__device__ float g_Hcat[B_*S_*DM];

union F4U { float4 f4; ull u2[2]; float f[4]; };

// ---------------------------------------------------------------------------
// Linear core: Y = X @ W^T + b for a 128-row slab. 384 threads. (unchanged)
// ---------------------------------------------------------------------------
__device__ __forceinline__ void lin_core(const float* __restrict__ X,
    const float* __restrict__ W, const float* __restrict__ bias,
    int row0, float scale, float* __restrict__ out, int headsplit)
{
    __shared__ float Ws[48*49];
    __shared__ float bs[48];
    __shared__ float Xs[128*48];
    int tid = threadIdx.x;
    for (int i = tid; i < 48*48; i += 384) Ws[(i/48)*49 + (i%48)] = W[i];
    if (tid < 48) bs[tid] = bias[tid];
    const float4* Xg4 = (const float4*)(X + row0*48);
    float4* Xs4 = (float4*)Xs;
    for (int i = tid; i < 1536; i += 384) Xs4[i] = Xg4[i];
    __syncthreads();

    int r0 = tid / 12, jg = tid % 12;
    float acc[4][4];
#pragma unroll
    for (int rr = 0; rr < 4; rr++)
#pragma unroll
        for (int jj = 0; jj < 4; jj++) acc[rr][jj] = bs[jg*4 + jj];

#pragma unroll 4
    for (int c = 0; c < 48; c++) {
        float xv[4], wv[4];
#pragma unroll
        for (int rr = 0; rr < 4; rr++) xv[rr] = Xs[(r0 + 32*rr)*48 + c];
#pragma unroll
        for (int jj = 0; jj < 4; jj++) wv[jj] = Ws[(jg*4 + jj)*49 + c];
#pragma unroll
        for (int rr = 0; rr < 4; rr++)
#pragma unroll
            for (int jj = 0; jj < 4; jj++)
                acc[rr][jj] = fmaf(xv[rr], wv[jj], acc[rr][jj]);
    }

    int j0 = jg * 4;
#pragma unroll
    for (int rr = 0; rr < 4; rr++) {
        int grow = row0 + r0 + 32*rr;
        float4 v = make_float4(acc[rr][0]*scale, acc[rr][1]*scale,
                               acc[rr][2]*scale, acc[rr][3]*scale);
        if (headsplit) {
            int b = grow >> 10, s = grow & 1023;
            int h = j0 >> 4,  d = j0 & 15;
            *(float4*)(out + ((b*NH + h)*S_ + s)*DK + d) = v;
        } else {
            *(float4*)(out + grow*48 + j0) = v;
        }
    }
}

__global__ __launch_bounds__(384) void qkv48(
    const float* __restrict__ Xq, const float* __restrict__ Wq, const float* __restrict__ bq,
    const float* __restrict__ Xk, const float* __restrict__ Wk, const float* __restrict__ bk,
    const float* __restrict__ Xv, const float* __restrict__ Wv, const float* __restrict__ bv)
{
    int m = blockIdx.y;
    const float *X, *W, *bb; float* dst; float scale;
    // Q scale folds 1/sqrt(dk) AND log2(e): attention uses ex2 directly.
    if (m == 0)      { X = Xq; W = Wq; bb = bq; dst = g_Q; scale = 0.25f * 1.4426950408889634f; }
    else if (m == 1) { X = Xk; W = Wk; bb = bk; dst = g_K; scale = 1.0f; }
    else             { X = Xv; W = Wv; bb = bv; dst = g_V; scale = 1.0f; }
    lin_core(X, W, bb, blockIdx.x * 128, scale, dst, 1);
}

__global__ __launch_bounds__(384) void proj48(
    const float* __restrict__ Wh, const float* __restrict__ bhp, float* __restrict__ out)
{
    lin_core((const float*)g_Hcat, Wh, bhp, blockIdx.x * 128, 1.0f, out, 0);
}

// ---------------------------------------------------------------------------
// Attention. Block = (32 q-rows, bh). 512 threads = 16 warps.
// Warp (rg, khalf): rows rg*4..rg*4+3, k-half khalf*512..+512. lane = k index.
// K/V in ONE smem buffer (stride 20 floats, conflict-free LDS.128),
// time-multiplexed: K for P1, V for P2b. E tile 32x1024 fp32, stride-1
// accesses only.
// P1: e = ex2(q.k) -> E + per-row lsum (in-warp butterfly = full row sum
//     for this k-half; halves combined via tiny smem array).
// P2a: A = E * inv, coalesced float4 stores.
// P2b: AV from E and V, lane=k with 4 rows in regs; lanes folded 4x by
//     2 butterfly steps, staged (8 lanes) into dead E area, 256-thread
//     cooperative reduce -> Hcat.
// ---------------------------------------------------------------------------
#define KVP   20
#define KV_F  (S_*KVP)                 // 20480
#define E_OFF KV_F
#define LSM_OFF (KV_F + 32*1024)       // 53248
#define INV_OFF (LSM_OFF + 64)
#define SM_FLOATS (INV_OFF + 32)       // 53344 floats = 213376 B

__global__ __launch_bounds__(512, 1) void attn_kernel(float* __restrict__ Aout)
{
    extern __shared__ float sm[];
    float* KV   = sm;
    float* Es   = sm + E_OFF;
    float* lsm  = sm + LSM_OFF;
    float* invs = sm + INV_OFF;

    int qt = blockIdx.x, bh = blockIdx.y;
    int tid = threadIdx.x, warp = tid >> 5, lane = tid & 31;
    int rg = warp >> 1, khalf = warp & 1;
    int q0 = qt * 32;
    int r0 = rg * 4;
    int kbase = khalf * 512;

    // ---- K -> smem (stride 20), Q -> regs ----
    const float4* Kg = (const float4*)(g_K + bh*(S_*DK));
    for (int i = tid; i < 4096; i += 512) {
        int row = i >> 2, c = i & 3;
        *(float4*)(KV + row*KVP + c*4) = Kg[i];
    }
    F4U qu[4][4];
    {
        const float4* qg = (const float4*)(g_Q + (bh*S_ + q0 + r0)*DK);
#pragma unroll
        for (int r = 0; r < 4; r++)
#pragma unroll
            for (int c = 0; c < 4; c++) qu[r][c].f4 = qg[r*4 + c];
    }
    __syncthreads();

    // ---- P1: scores -> exp -> E smem + row sums ----
    float lsum[4] = {0.f, 0.f, 0.f, 0.f};
#pragma unroll 1
    for (int it = 0; it < 16; it++) {
        int k = kbase + it*32 + lane;
        F4U k0, k1, k2, k3;
        const float4* kr = (const float4*)(KV + k*KVP);
        k0.f4 = kr[0]; k1.f4 = kr[1]; k2.f4 = kr[2]; k3.f4 = kr[3];
#pragma unroll
        for (int r = 0; r < 4; r++) {
            ull a, b;
            asm("mul.rn.f32x2 %0,%1,%2;"    : "=l"(a) : "l"(qu[r][0].u2[0]), "l"(k0.u2[0]));
            asm("fma.rn.f32x2 %0,%1,%2,%0;" : "+l"(a) : "l"(qu[r][0].u2[1]), "l"(k0.u2[1]));
            asm("fma.rn.f32x2 %0,%1,%2,%0;" : "+l"(a) : "l"(qu[r][1].u2[0]), "l"(k1.u2[0]));
            asm("fma.rn.f32x2 %0,%1,%2,%0;" : "+l"(a) : "l"(qu[r][1].u2[1]), "l"(k1.u2[1]));
            asm("mul.rn.f32x2 %0,%1,%2;"    : "=l"(b) : "l"(qu[r][2].u2[0]), "l"(k2.u2[0]));
            asm("fma.rn.f32x2 %0,%1,%2,%0;" : "+l"(b) : "l"(qu[r][2].u2[1]), "l"(k2.u2[1]));
            asm("fma.rn.f32x2 %0,%1,%2,%0;" : "+l"(b) : "l"(qu[r][3].u2[0]), "l"(k3.u2[0]));
            asm("fma.rn.f32x2 %0,%1,%2,%0;" : "+l"(b) : "l"(qu[r][3].u2[1]), "l"(k3.u2[1]));
            asm("add.rn.f32x2 %0,%0,%1;"    : "+l"(a) : "l"(b));
            float lo, hi;
            asm("mov.b64 {%0,%1},%2;" : "=f"(lo), "=f"(hi) : "l"(a));
            float s = lo + hi;
            float e;
            asm("ex2.approx.f32 %0,%1;" : "=f"(e) : "f"(s));
            Es[(r0 + r)*1024 + k] = e;
            lsum[r] += e;
        }
    }
    // in-warp row sums (full sum over this k-half)
#pragma unroll
    for (int r = 0; r < 4; r++) {
        float v = lsum[r];
#pragma unroll
        for (int o = 16; o > 0; o >>= 1) v += __shfl_xor_sync(0xffffffffu, v, o);
        lsum[r] = v;
    }
    if (lane == 0) {
#pragma unroll
        for (int r = 0; r < 4; r++) lsm[khalf*32 + r0 + r] = lsum[r];
    }
    __syncthreads();       // K dead, E + lsm ready

    // ---- V overwrites K; 32 threads compute inverses ----
    const float4* Vg = (const float4*)(g_V + bh*(S_*DK));
    for (int i = tid; i < 4096; i += 512) {
        int row = i >> 2, c = i & 3;
        *(float4*)(KV + row*KVP + c*4) = Vg[i];
    }
    if (tid < 32) invs[tid] = 1.0f / (lsm[tid] + lsm[32 + tid]);
    __syncthreads();       // V + invs ready

    // ---- P2a: A = E * inv, warp handles rows 2*warp, 2*warp+1 ----
#pragma unroll
    for (int rr = 0; rr < 2; rr++) {
        int row = warp*2 + rr;
        float iv = invs[row];
        const float4* er = (const float4*)(Es + row*1024);
        float4* ar = (float4*)(Aout + (bh*S_ + q0 + row)*S_);
#pragma unroll
        for (int it = 0; it < 8; it++) {
            float4 t = er[it*32 + lane];
            t.x *= iv; t.y *= iv; t.z *= iv; t.w *= iv;
            ar[it*32 + lane] = t;
        }
    }

    // ---- P2b: AV, lane=k, 4 rows in regs ----
    ull acc[4][8];
#pragma unroll
    for (int r = 0; r < 4; r++)
#pragma unroll
        for (int j = 0; j < 8; j++) acc[r][j] = 0ULL;

#pragma unroll 1
    for (int it = 0; it < 16; it++) {
        int k = kbase + it*32 + lane;
        F4U v0, v1, v2, v3;
        const float4* vr = (const float4*)(KV + k*KVP);
        v0.f4 = vr[0]; v1.f4 = vr[1]; v2.f4 = vr[2]; v3.f4 = vr[3];
#pragma unroll
        for (int r = 0; r < 4; r++) {
            float e = Es[(r0 + r)*1024 + k];
            ull ee; asm("mov.b64 %0,{%1,%1};" : "=l"(ee) : "f"(e));
            asm("fma.rn.f32x2 %0,%1,%2,%0;" : "+l"(acc[r][0]) : "l"(ee), "l"(v0.u2[0]));
            asm("fma.rn.f32x2 %0,%1,%2,%0;" : "+l"(acc[r][1]) : "l"(ee), "l"(v0.u2[1]));
            asm("fma.rn.f32x2 %0,%1,%2,%0;" : "+l"(acc[r][2]) : "l"(ee), "l"(v1.u2[0]));
            asm("fma.rn.f32x2 %0,%1,%2,%0;" : "+l"(acc[r][3]) : "l"(ee), "l"(v1.u2[1]));
            asm("fma.rn.f32x2 %0,%1,%2,%0;" : "+l"(acc[r][4]) : "l"(ee), "l"(v2.u2[0]));
            asm("fma.rn.f32x2 %0,%1,%2,%0;" : "+l"(acc[r][5]) : "l"(ee), "l"(v2.u2[1]));
            asm("fma.rn.f32x2 %0,%1,%2,%0;" : "+l"(acc[r][6]) : "l"(ee), "l"(v3.u2[0]));
            asm("fma.rn.f32x2 %0,%1,%2,%0;" : "+l"(acc[r][7]) : "l"(ee), "l"(v3.u2[1]));
        }
    }

    // unpack + fold lanes 4x (xor16, xor8): lanes 0..7 hold 4-lane-group sums
    float fa[4][16];
#pragma unroll
    for (int r = 0; r < 4; r++)
#pragma unroll
        for (int j = 0; j < 8; j++)
            asm("mov.b64 {%0,%1},%2;" : "=f"(fa[r][2*j]), "=f"(fa[r][2*j+1]) : "l"(acc[r][j]));
#pragma unroll
    for (int o = 16; o >= 8; o >>= 1)
#pragma unroll
        for (int r = 0; r < 4; r++)
#pragma unroll
            for (int j = 0; j < 16; j++)
                fa[r][j] += __shfl_xor_sync(0xffffffffu, fa[r][j], o);

    __syncthreads();       // all P2b E reads done: E area reusable as stage

    // stage: [row 32][d2 8] x [khalf 2][lanegrp 8] with pad -> stride 17 float2
    float2* stg = (float2*)Es;
    if (lane < 8) {
#pragma unroll
        for (int r = 0; r < 4; r++)
#pragma unroll
            for (int d2 = 0; d2 < 8; d2++)
                stg[((r0 + r)*8 + d2)*17 + khalf*8 + lane] =
                    make_float2(fa[r][2*d2], fa[r][2*d2 + 1]);
    }
    __syncthreads();

    // cooperative reduce: 256 threads, one (row, d2) each
    if (tid < 256) {
        int row = tid >> 3, d2 = tid & 7;
        const float2* p = (const float2*)Es + (row*8 + d2)*17;
        float sx = 0.f, sy = 0.f;
#pragma unroll
        for (int j = 0; j < 16; j++) { float2 t = p[j]; sx += t.x; sy += t.y; }
        float iv = invs[row];
        int b = bh / NH, h = bh - b*NH;
        *(float2*)(g_Hcat + (b*S_ + q0 + row)*DM + h*DK + d2*2) =
            make_float2(sx*iv, sy*iv);
    }
}

// ---------------------------------------------------------------------------
extern "C" void kernel_launch(void* const* d_in, const int* in_sizes, int n_in,
                              void* d_out, int out_size)
{
    const float* Xq = (const float*)d_in[0];
    const float* Xk = (const float*)d_in[1];
    const float* Xv = (const float*)d_in[2];
    const float* Wq = (const float*)d_in[3];
    const float* bq = (const float*)d_in[4];
    const float* Wk = (const float*)d_in[5];
    const float* bk = (const float*)d_in[6];
    const float* Wv = (const float*)d_in[7];
    const float* bv = (const float*)d_in[8];
    const float* Wh = (const float*)d_in[9];
    const float* bh = (const float*)d_in[10];

    float* outH = (float*)d_out;
    float* outA = (float*)d_out + H_ELEMS;

    const int smem_bytes = SM_FLOATS * 4;   // 213376 B
    cudaFuncSetAttribute(attn_kernel, cudaFuncAttributeMaxDynamicSharedMemorySize, smem_bytes);

    qkv48<<<dim3(256, 3), 384>>>(Xq, Wq, bq, Xk, Wk, bk, Xv, Wv, bv);
    attn_kernel<<<dim3(32, BH_), 512, smem_bytes>>>(outA);
    proj48<<<256, 384>>>(Wh, bh, outH);
}

// round 8
// speedup vs baseline: 1.0713x; 1.0228x over previous
#include <cuda_runtime.h>
#include <math.h>

#define B_   32
#define S_   1024
#define DM   48
#define NH   3
#define DK   16
#define BH_  (B_*NH)            // 96
#define H_ELEMS (B_*S_*DM)      // 1572864

typedef unsigned long long ull;

// Scratch (no allocations allowed)
__device__ float g_Q[BH_*S_*DK];
__device__ float g_K[BH_*S_*DK];
__device__ float g_V[BH_*S_*DK];
__device__ float g_Hcat[B_*S_*DM];

union F4U { float4 f4; ull u2[2]; float f[4]; };

// ---------------------------------------------------------------------------
// Linear core: Y = X @ W^T + b for a 128-row slab. 384 threads.
// X rows read as float4 (LDS.128), W scalar-broadcast.
// ---------------------------------------------------------------------------
__device__ __forceinline__ void lin_core(const float* __restrict__ X,
    const float* __restrict__ W, const float* __restrict__ bias,
    int row0, float scale, float* __restrict__ out, int headsplit)
{
    __shared__ float Ws[48*49];
    __shared__ float bs[48];
    __shared__ __align__(16) float Xs[128*48];
    int tid = threadIdx.x;
    for (int i = tid; i < 48*48; i += 384) Ws[(i/48)*49 + (i%48)] = W[i];
    if (tid < 48) bs[tid] = bias[tid];
    const float4* Xg4 = (const float4*)(X + row0*48);
    float4* Xs4 = (float4*)Xs;
    for (int i = tid; i < 1536; i += 384) Xs4[i] = Xg4[i];
    __syncthreads();

    int r0 = tid / 12, jg = tid % 12;
    float acc[4][4];
#pragma unroll
    for (int rr = 0; rr < 4; rr++)
#pragma unroll
        for (int jj = 0; jj < 4; jj++) acc[rr][jj] = bs[jg*4 + jj];

#pragma unroll 3
    for (int c4 = 0; c4 < 12; c4++) {
        float4 xv4[4];
#pragma unroll
        for (int rr = 0; rr < 4; rr++)
            xv4[rr] = *(const float4*)&Xs[(r0 + 32*rr)*48 + c4*4];
#pragma unroll
        for (int jj = 0; jj < 4; jj++) {
            const float* wr = &Ws[(jg*4 + jj)*49 + c4*4];
            float w0 = wr[0], w1 = wr[1], w2 = wr[2], w3 = wr[3];
#pragma unroll
            for (int rr = 0; rr < 4; rr++) {
                acc[rr][jj] = fmaf(xv4[rr].x, w0, acc[rr][jj]);
                acc[rr][jj] = fmaf(xv4[rr].y, w1, acc[rr][jj]);
                acc[rr][jj] = fmaf(xv4[rr].z, w2, acc[rr][jj]);
                acc[rr][jj] = fmaf(xv4[rr].w, w3, acc[rr][jj]);
            }
        }
    }

    int j0 = jg * 4;
#pragma unroll
    for (int rr = 0; rr < 4; rr++) {
        int grow = row0 + r0 + 32*rr;
        float4 v = make_float4(acc[rr][0]*scale, acc[rr][1]*scale,
                               acc[rr][2]*scale, acc[rr][3]*scale);
        if (headsplit) {
            int b = grow >> 10, s = grow & 1023;
            int h = j0 >> 4,  d = j0 & 15;
            *(float4*)(out + ((b*NH + h)*S_ + s)*DK + d) = v;
        } else {
            *(float4*)(out + grow*48 + j0) = v;
        }
    }
}

__global__ __launch_bounds__(384) void qkv48(
    const float* __restrict__ Xq, const float* __restrict__ Wq, const float* __restrict__ bq,
    const float* __restrict__ Xk, const float* __restrict__ Wk, const float* __restrict__ bk,
    const float* __restrict__ Xv, const float* __restrict__ Wv, const float* __restrict__ bv)
{
    int m = blockIdx.y;
    const float *X, *W, *bb; float* dst; float scale;
    // Q scale folds 1/sqrt(dk) AND log2(e): attention uses ex2 directly.
    if (m == 0)      { X = Xq; W = Wq; bb = bq; dst = g_Q; scale = 0.25f * 1.4426950408889634f; }
    else if (m == 1) { X = Xk; W = Wk; bb = bk; dst = g_K; scale = 1.0f; }
    else             { X = Xv; W = Wv; bb = bv; dst = g_V; scale = 1.0f; }
    lin_core(X, W, bb, blockIdx.x * 128, scale, dst, 1);
}

__global__ __launch_bounds__(384) void proj48(
    const float* __restrict__ Wh, const float* __restrict__ bhp, float* __restrict__ out)
{
    lin_core((const float*)g_Hcat, Wh, bhp, blockIdx.x * 128, 1.0f, out, 0);
}

// ---------------------------------------------------------------------------
// Attention, single-pass. Block = (32 q-rows, bh). 512 threads = 16 warps.
// Warp w owns rows 2w, 2w+1 over the FULL k range; lane = k (mod 32).
// K,V interleaved per k-row: 36 floats (K[0..15], V[16..31], pad 4)
//   -> lane-varying LDS.128 provably conflict-free (4k mod 32 pattern).
// Main loop: e = ex2(q.k) -> STG to A (unnormalized, coalesced) + row sum
//   + AV accumulate (unnormalized) fused. NO second exp / NO E tile.
// Then: row-sum butterfly -> inv; in-place rescale of this block's A rows
//   (L2-resident: 148 blocks x 128 KB ~ 19 MB << 126 MB L2, so re-read hits
//   L2 and the dirty-line overwrite collapses to one DRAM writeback);
// AV folded 4x by 2 butterflies, staged, 256-thread reduce -> Hcat.
// ---------------------------------------------------------------------------
#define KVP     36
#define KV_F    (S_*KVP)               // 36864
#define QS_OFF  KV_F                   // 512 floats (32x16)
#define STG_OFF (QS_OFF + 512)         // stage: 32 rows x 8 d2 x 9 float2 pad
#define STG_F   (32*8*9*2)             // 4608 floats
#define LSM_OFF (STG_OFF + STG_F)
#define INV_OFF (LSM_OFF + 32)
#define SM_FLOATS (INV_OFF + 32)       // 42048 floats = 168192 B

__global__ __launch_bounds__(512, 1) void attn_kernel(float* __restrict__ Aout)
{
    extern __shared__ __align__(16) float sm[];
    float* KV   = sm;
    float* Qs   = sm + QS_OFF;
    float2* stg = (float2*)(sm + STG_OFF);
    float* lsm  = sm + LSM_OFF;
    float* invs = sm + INV_OFF;

    int qt = blockIdx.x, bh = blockIdx.y;
    int tid = threadIdx.x, warp = tid >> 5, lane = tid & 31;
    int q0 = qt * 32;
    int r0 = warp * 2;                 // this warp's first row (of 2)

    // ---- K,V -> interleaved smem; Q tile -> smem ----
    {
        const float4* Kg = (const float4*)(g_K + bh*(S_*DK));
        const float4* Vg = (const float4*)(g_V + bh*(S_*DK));
        // i = c*1024 + row, c in 0..7 (c<4 -> K slot c, else V slot c-4)
        for (int i = tid; i < 8192; i += 512) {
            int c = i >> 10, row = i & 1023;
            if (c < 4) *(float4*)(KV + row*KVP + c*4)        = Kg[row*4 + c];
            else       *(float4*)(KV + row*KVP + 16 + (c-4)*4) = Vg[row*4 + (c-4)];
        }
        if (tid < 128) {
            ((float4*)Qs)[tid] = ((const float4*)(g_Q + (bh*S_ + q0)*DK))[tid];
        }
    }
    __syncthreads();

    // Q rows for this warp -> regs (broadcast smem reads)
    F4U qu[2][4];
#pragma unroll
    for (int r = 0; r < 2; r++)
#pragma unroll
        for (int c = 0; c < 4; c++)
            qu[r][c].f4 = *(const float4*)&Qs[(r0 + r)*16 + c*4];

    // ---- main loop: e -> A (unnormalized) + row sums + AV ----
    float lsum[2] = {0.f, 0.f};
    ull acc[2][8];
#pragma unroll
    for (int r = 0; r < 2; r++)
#pragma unroll
        for (int j = 0; j < 8; j++) acc[r][j] = 0ULL;

    float* A0 = Aout + (bh*S_ + q0 + r0)*S_ + lane;
    float* A1 = A0 + S_;

#pragma unroll 2
    for (int it = 0; it < 32; it++) {
        int k = it*32 + lane;
        const float4* kr = (const float4*)(KV + k*KVP);
        F4U k0, k1, k2, k3, v0, v1, v2, v3;
        k0.f4 = kr[0]; k1.f4 = kr[1]; k2.f4 = kr[2]; k3.f4 = kr[3];
        v0.f4 = kr[4]; v1.f4 = kr[5]; v2.f4 = kr[6]; v3.f4 = kr[7];

        float ev[2];
#pragma unroll
        for (int r = 0; r < 2; r++) {
            ull a, b;
            asm("mul.rn.f32x2 %0,%1,%2;"    : "=l"(a) : "l"(qu[r][0].u2[0]), "l"(k0.u2[0]));
            asm("fma.rn.f32x2 %0,%1,%2,%0;" : "+l"(a) : "l"(qu[r][0].u2[1]), "l"(k0.u2[1]));
            asm("fma.rn.f32x2 %0,%1,%2,%0;" : "+l"(a) : "l"(qu[r][1].u2[0]), "l"(k1.u2[0]));
            asm("fma.rn.f32x2 %0,%1,%2,%0;" : "+l"(a) : "l"(qu[r][1].u2[1]), "l"(k1.u2[1]));
            asm("mul.rn.f32x2 %0,%1,%2;"    : "=l"(b) : "l"(qu[r][2].u2[0]), "l"(k2.u2[0]));
            asm("fma.rn.f32x2 %0,%1,%2,%0;" : "+l"(b) : "l"(qu[r][2].u2[1]), "l"(k2.u2[1]));
            asm("fma.rn.f32x2 %0,%1,%2,%0;" : "+l"(b) : "l"(qu[r][3].u2[0]), "l"(k3.u2[0]));
            asm("fma.rn.f32x2 %0,%1,%2,%0;" : "+l"(b) : "l"(qu[r][3].u2[1]), "l"(k3.u2[1]));
            asm("add.rn.f32x2 %0,%0,%1;"    : "+l"(a) : "l"(b));
            float lo, hi;
            asm("mov.b64 {%0,%1},%2;" : "=f"(lo), "=f"(hi) : "l"(a));
            float s = lo + hi;
            float e;
            asm("ex2.approx.f32 %0,%1;" : "=f"(e) : "f"(s));
            ev[r] = e;
            lsum[r] += e;

            ull ee; asm("mov.b64 %0,{%1,%1};" : "=l"(ee) : "f"(e));
            asm("fma.rn.f32x2 %0,%1,%2,%0;" : "+l"(acc[r][0]) : "l"(ee), "l"(v0.u2[0]));
            asm("fma.rn.f32x2 %0,%1,%2,%0;" : "+l"(acc[r][1]) : "l"(ee), "l"(v0.u2[1]));
            asm("fma.rn.f32x2 %0,%1,%2,%0;" : "+l"(acc[r][2]) : "l"(ee), "l"(v1.u2[0]));
            asm("fma.rn.f32x2 %0,%1,%2,%0;" : "+l"(acc[r][3]) : "l"(ee), "l"(v1.u2[1]));
            asm("fma.rn.f32x2 %0,%1,%2,%0;" : "+l"(acc[r][4]) : "l"(ee), "l"(v2.u2[0]));
            asm("fma.rn.f32x2 %0,%1,%2,%0;" : "+l"(acc[r][5]) : "l"(ee), "l"(v2.u2[1]));
            asm("fma.rn.f32x2 %0,%1,%2,%0;" : "+l"(acc[r][6]) : "l"(ee), "l"(v3.u2[0]));
            asm("fma.rn.f32x2 %0,%1,%2,%0;" : "+l"(acc[r][7]) : "l"(ee), "l"(v3.u2[1]));
        }
        A0[it*32] = ev[0];             // unnormalized; rescaled below (L2 hit)
        A1[it*32] = ev[1];
    }

    // ---- row sums: in-warp butterfly (lane = k mod 32) ----
#pragma unroll
    for (int r = 0; r < 2; r++) {
        float v = lsum[r];
#pragma unroll
        for (int o = 16; o > 0; o >>= 1) v += __shfl_xor_sync(0xffffffffu, v, o);
        if (lane == 0) lsm[r0 + r] = v;
    }

    // ---- AV fold x4 (xor16, xor8): lanes 0..7 hold 4-lane-group sums ----
    float fa[2][16];
#pragma unroll
    for (int r = 0; r < 2; r++)
#pragma unroll
        for (int j = 0; j < 8; j++)
            asm("mov.b64 {%0,%1},%2;" : "=f"(fa[r][2*j]), "=f"(fa[r][2*j+1]) : "l"(acc[r][j]));
#pragma unroll
    for (int o = 16; o >= 8; o >>= 1)
#pragma unroll
        for (int r = 0; r < 2; r++)
#pragma unroll
            for (int j = 0; j < 16; j++)
                fa[r][j] += __shfl_xor_sync(0xffffffffu, fa[r][j], o);

    if (lane < 8) {
#pragma unroll
        for (int r = 0; r < 2; r++)
#pragma unroll
            for (int d2 = 0; d2 < 8; d2++)
                stg[((r0 + r)*8 + d2)*9 + lane] = make_float2(fa[r][2*d2], fa[r][2*d2+1]);
    }

    __syncthreads();      // A stores visible block-wide, lsm + stage ready
    if (tid < 32) invs[tid] = 1.0f / lsm[tid];
    __syncthreads();      // invs ready

    // ---- Hcat: 256-thread cooperative reduce over 8 staged partials ----
    if (tid < 256) {
        int row = tid >> 3, d2 = tid & 7;
        const float2* p = stg + (row*8 + d2)*9;
        float sx = 0.f, sy = 0.f;
#pragma unroll
        for (int j = 0; j < 8; j++) { float2 t = p[j]; sx += t.x; sy += t.y; }
        float iv = invs[row];
        int b = bh / NH, h = bh - b*NH;
        *(float2*)(g_Hcat + (b*S_ + q0 + row)*DM + h*DK + d2*2) =
            make_float2(sx*iv, sy*iv);
    }

    // ---- in-place A rescale: this block's rows, still L2-resident ----
    {
        float iv0 = invs[r0], iv1 = invs[r0 + 1];
        float4* R0 = (float4*)(Aout + (bh*S_ + q0 + r0)*S_);
        float4* R1 = (float4*)(Aout + (bh*S_ + q0 + r0 + 1)*S_);
#pragma unroll
        for (int i = 0; i < 8; i++) {
            int idx = i*32 + lane;
            float4 t0 = R0[idx], t1 = R1[idx];
            t0.x *= iv0; t0.y *= iv0; t0.z *= iv0; t0.w *= iv0;
            t1.x *= iv1; t1.y *= iv1; t1.z *= iv1; t1.w *= iv1;
            R0[idx] = t0; R1[idx] = t1;
        }
    }
}

// ---------------------------------------------------------------------------
extern "C" void kernel_launch(void* const* d_in, const int* in_sizes, int n_in,
                              void* d_out, int out_size)
{
    const float* Xq = (const float*)d_in[0];
    const float* Xk = (const float*)d_in[1];
    const float* Xv = (const float*)d_in[2];
    const float* Wq = (const float*)d_in[3];
    const float* bq = (const float*)d_in[4];
    const float* Wk = (const float*)d_in[5];
    const float* bk = (const float*)d_in[6];
    const float* Wv = (const float*)d_in[7];
    const float* bv = (const float*)d_in[8];
    const float* Wh = (const float*)d_in[9];
    const float* bh = (const float*)d_in[10];

    float* outH = (float*)d_out;
    float* outA = (float*)d_out + H_ELEMS;

    const int smem_bytes = SM_FLOATS * 4;   // 168192 B
    cudaFuncSetAttribute(attn_kernel, cudaFuncAttributeMaxDynamicSharedMemorySize, smem_bytes);

    qkv48<<<dim3(256, 3), 384>>>(Xq, Wq, bq, Xk, Wk, bk, Xv, Wv, bv);
    attn_kernel<<<dim3(32, BH_), 512, smem_bytes>>>(outA);
    proj48<<<256, 384>>>(Wh, bh, outH);
}

// round 10
// speedup vs baseline: 2.3156x; 2.1616x over previous
#include <cuda_runtime.h>
#include <cuda_bf16.h>
#include <math.h>
#include <stdint.h>

#define B_   32
#define S_   1024
#define DM   48
#define NH   3
#define DK   16
#define BH_  (B_*NH)            // 96
#define H_ELEMS (B_*S_*DM)      // 1572864

typedef unsigned long long ull;

// Scratch (no allocations allowed)
__device__ float g_Q[BH_*S_*DK];
__device__ float g_K[BH_*S_*DK];
__device__ float g_V[BH_*S_*DK];
__device__ float g_Hcat[B_*S_*DM];

// ---------------------------------------------------------------------------
// Linear kernels (unchanged from R8 — known good)
// ---------------------------------------------------------------------------
__device__ __forceinline__ void lin_core(const float* __restrict__ X,
    const float* __restrict__ W, const float* __restrict__ bias,
    int row0, float scale, float* __restrict__ out, int headsplit)
{
    __shared__ float Ws[48*49];
    __shared__ float bs[48];
    __shared__ __align__(16) float Xs[128*48];
    int tid = threadIdx.x;
    for (int i = tid; i < 48*48; i += 384) Ws[(i/48)*49 + (i%48)] = W[i];
    if (tid < 48) bs[tid] = bias[tid];
    const float4* Xg4 = (const float4*)(X + row0*48);
    float4* Xs4 = (float4*)Xs;
    for (int i = tid; i < 1536; i += 384) Xs4[i] = Xg4[i];
    __syncthreads();

    int r0 = tid / 12, jg = tid % 12;
    float acc[4][4];
#pragma unroll
    for (int rr = 0; rr < 4; rr++)
#pragma unroll
        for (int jj = 0; jj < 4; jj++) acc[rr][jj] = bs[jg*4 + jj];

#pragma unroll 3
    for (int c4 = 0; c4 < 12; c4++) {
        float4 xv4[4];
#pragma unroll
        for (int rr = 0; rr < 4; rr++)
            xv4[rr] = *(const float4*)&Xs[(r0 + 32*rr)*48 + c4*4];
#pragma unroll
        for (int jj = 0; jj < 4; jj++) {
            const float* wr = &Ws[(jg*4 + jj)*49 + c4*4];
            float w0 = wr[0], w1 = wr[1], w2 = wr[2], w3 = wr[3];
#pragma unroll
            for (int rr = 0; rr < 4; rr++) {
                acc[rr][jj] = fmaf(xv4[rr].x, w0, acc[rr][jj]);
                acc[rr][jj] = fmaf(xv4[rr].y, w1, acc[rr][jj]);
                acc[rr][jj] = fmaf(xv4[rr].z, w2, acc[rr][jj]);
                acc[rr][jj] = fmaf(xv4[rr].w, w3, acc[rr][jj]);
            }
        }
    }

    int j0 = jg * 4;
#pragma unroll
    for (int rr = 0; rr < 4; rr++) {
        int grow = row0 + r0 + 32*rr;
        float4 v = make_float4(acc[rr][0]*scale, acc[rr][1]*scale,
                               acc[rr][2]*scale, acc[rr][3]*scale);
        if (headsplit) {
            int b = grow >> 10, s = grow & 1023;
            int h = j0 >> 4,  d = j0 & 15;
            *(float4*)(out + ((b*NH + h)*S_ + s)*DK + d) = v;
        } else {
            *(float4*)(out + grow*48 + j0) = v;
        }
    }
}

__global__ __launch_bounds__(384) void qkv48(
    const float* __restrict__ Xq, const float* __restrict__ Wq, const float* __restrict__ bq,
    const float* __restrict__ Xk, const float* __restrict__ Wk, const float* __restrict__ bk,
    const float* __restrict__ Xv, const float* __restrict__ Wv, const float* __restrict__ bv)
{
    int m = blockIdx.y;
    const float *X, *W, *bb; float* dst; float scale;
    // Q scale folds 1/sqrt(dk) AND log2(e): attention uses ex2 directly.
    if (m == 0)      { X = Xq; W = Wq; bb = bq; dst = g_Q; scale = 0.25f * 1.4426950408889634f; }
    else if (m == 1) { X = Xk; W = Wk; bb = bk; dst = g_K; scale = 1.0f; }
    else             { X = Xv; W = Wv; bb = bv; dst = g_V; scale = 1.0f; }
    lin_core(X, W, bb, blockIdx.x * 128, scale, dst, 1);
}

__global__ __launch_bounds__(384) void proj48(
    const float* __restrict__ Wh, const float* __restrict__ bhp, float* __restrict__ out)
{
    lin_core((const float*)g_Hcat, Wh, bhp, blockIdx.x * 128, 1.0f, out, 0);
}

// ---------------------------------------------------------------------------
// split fp32 pair -> (bf16x2 hi, bf16x2 lo). Low 16 bits = first value.
// ---------------------------------------------------------------------------
__device__ __forceinline__ void split2(float e0, float e1, uint32_t& h2, uint32_t& l2) {
    uint32_t h;
    asm("cvt.rn.bf16x2.f32 %0, %1, %2;" : "=r"(h) : "f"(e1), "f"(e0));
    float h0 = __uint_as_float(h << 16);
    float h1 = __uint_as_float(h & 0xFFFF0000u);
    uint32_t l;
    asm("cvt.rn.bf16x2.f32 %0, %1, %2;" : "=r"(l) : "f"(e1 - h1), "f"(e0 - h0));
    h2 = h; l2 = l;
}

// mma.sync m16n8k16 row.col f32.bf16.bf16.f32, D accumulates in place.
__device__ __forceinline__ void mma_bf16(float d[4], const uint32_t a[4], const uint32_t b[2]) {
    asm volatile(
        "mma.sync.aligned.m16n8k16.row.col.f32.bf16.bf16.f32 "
        "{%0,%1,%2,%3}, {%4,%5,%6,%7}, {%8,%9}, {%0,%1,%2,%3};"
        : "+f"(d[0]), "+f"(d[1]), "+f"(d[2]), "+f"(d[3])
        : "r"(a[0]), "r"(a[1]), "r"(a[2]), "r"(a[3]), "r"(b[0]), "r"(b[1]));
}

// smem layout (u32 units): khi[8192] klo[8192] vhi[8192] vlo[8192] stage[4096]
#define SMO_KHI   0
#define SMO_KLO   8192
#define SMO_VHI   16384
#define SMO_VLO   24576
#define SMO_STAGE 32768
#define SMEM_BYTES ((32768 + 4096) * 4)   // 147456

// ---------------------------------------------------------------------------
// Tensor-core attention via mma.sync (plain sm_103 target — no tcgen05).
// CTA = (qtile of 256 rows, bh). 512 thr = 16 warps; warp owns 16 q rows.
// K/V pre-split to bf16 hi/lo fragments in smem (shared by all warps).
// Pass 1: scores = 3x split MMA -> ex2 -> row sums (quad reduce) -> inv.
// Pass 2: recompute scores, normalize, coalesced A float2 stores, repack
//         normalized e into A-fragments (lane-local), AV = 3x split MMA per
//         d-tile into fp32 C frags. Epilogue: Hcat direct (pre-normalized).
// ---------------------------------------------------------------------------
__global__ __launch_bounds__(512, 1) void attn_mma(float* __restrict__ Aout)
{
    extern __shared__ __align__(16) uint32_t smu[];
    uint32_t* khi = smu + SMO_KHI;
    uint32_t* klo = smu + SMO_KLO;
    uint32_t* vhi = smu + SMO_VHI;
    uint32_t* vlo = smu + SMO_VLO;
    float* stage  = (float*)(smu + SMO_STAGE);

    int qt = blockIdx.x, bh = blockIdx.y;
    int tid = threadIdx.x, warp = tid >> 5, lane = tid & 31;
    int tg = lane & 3, gid = lane >> 2;
    int q0 = qt * 256;

    // ---- build K fragments (4 rounds of 256 seq rows) ----
    const float4* Kg4 = (const float4*)(g_K + bh*(S_*DK));
    for (int r = 0; r < 4; r++) {
        for (int i = tid; i < 1024; i += 512)
            ((float4*)stage)[i] = Kg4[r*1024 + i];
        __syncthreads();
        for (int e = tid; e < 2048; e += 512) {
            int tl = e >> 6, rem = e & 63, reg = rem >> 5, ln = rem & 31;
            int krow = tl*8 + (ln >> 2), dk = reg*8 + (ln & 3)*2;
            float2 v = *(const float2*)(stage + krow*16 + dk);
            uint32_t h, l; split2(v.x, v.y, h, l);
            int t = r*32 + tl;
            khi[(t*32 + ln)*2 + reg] = h;
            klo[(t*32 + ln)*2 + reg] = l;
        }
        __syncthreads();
    }
    // ---- build V fragments (4 rounds) ----
    const float4* Vg4 = (const float4*)(g_V + bh*(S_*DK));
    for (int r = 0; r < 4; r++) {
        for (int i = tid; i < 1024; i += 512)
            ((float4*)stage)[i] = Vg4[r*1024 + i];
        __syncthreads();
        for (int e = tid; e < 2048; e += 512) {
            int kcl = e >> 7, rem = e & 127, t = rem >> 6, reg = (rem >> 5) & 1, ln = rem & 31;
            int klc = kcl*16 + reg*8 + (ln & 3)*2, d = t*8 + (ln >> 2);
            float v0 = stage[klc*16 + d];
            float v1 = stage[(klc + 1)*16 + d];
            uint32_t h, l; split2(v0, v1, h, l);
            int kc = r*16 + kcl;
            vhi[((kc*2 + t)*32 + ln)*2 + reg] = h;
            vlo[((kc*2 + t)*32 + ln)*2 + reg] = l;
        }
        __syncthreads();
    }

    // ---- Q A-fragment (m16 x k16 = one MMA step), split hi/lo ----
    uint32_t qhi[4], qlo[4];
    {
        const float* Qp = g_Q + (bh*S_ + q0 + warp*16)*DK;
        float2 x;
        x = *(const float2*)(Qp + gid*16 + tg*2);           split2(x.x, x.y, qhi[0], qlo[0]);
        x = *(const float2*)(Qp + (gid+8)*16 + tg*2);       split2(x.x, x.y, qhi[1], qlo[1]);
        x = *(const float2*)(Qp + gid*16 + tg*2 + 8);       split2(x.x, x.y, qhi[2], qlo[2]);
        x = *(const float2*)(Qp + (gid+8)*16 + tg*2 + 8);   split2(x.x, x.y, qhi[3], qlo[3]);
    }

    // ---- pass 1: row sums ----
    float ls0 = 0.f, ls1 = 0.f;
#pragma unroll 2
    for (int t = 0; t < 128; t++) {
        uint32_t kb[2], kl2[2];
        *(uint2*)kb  = *(const uint2*)(khi + (t*32 + lane)*2);
        *(uint2*)kl2 = *(const uint2*)(klo + (t*32 + lane)*2);
        float d[4] = {0.f, 0.f, 0.f, 0.f};
        mma_bf16(d, qhi, kb);
        mma_bf16(d, qhi, kl2);
        mma_bf16(d, qlo, kb);
        float e0, e1, e2, e3;
        asm("ex2.approx.f32 %0,%1;" : "=f"(e0) : "f"(d[0]));
        asm("ex2.approx.f32 %0,%1;" : "=f"(e1) : "f"(d[1]));
        asm("ex2.approx.f32 %0,%1;" : "=f"(e2) : "f"(d[2]));
        asm("ex2.approx.f32 %0,%1;" : "=f"(e3) : "f"(d[3]));
        ls0 += e0 + e1;
        ls1 += e2 + e3;
    }
    ls0 += __shfl_xor_sync(0xffffffffu, ls0, 1);
    ls0 += __shfl_xor_sync(0xffffffffu, ls0, 2);
    ls1 += __shfl_xor_sync(0xffffffffu, ls1, 1);
    ls1 += __shfl_xor_sync(0xffffffffu, ls1, 2);
    float inv0 = 1.0f / ls0, inv1 = 1.0f / ls1;

    // ---- pass 2: normalized A stores + AV ----
    float cA[4] = {0.f, 0.f, 0.f, 0.f};   // d cols 0..7
    float cB[4] = {0.f, 0.f, 0.f, 0.f};   // d cols 8..15
    float* Ab = Aout + ((size_t)(bh*S_ + q0 + warp*16))*S_;
    float* Ar1 = Ab + (size_t)gid*S_ + tg*2;
    float* Ar2 = Ab + (size_t)(gid+8)*S_ + tg*2;

#pragma unroll 1
    for (int kc = 0; kc < 64; kc++) {
        float e[2][4];
#pragma unroll
        for (int s = 0; s < 2; s++) {
            int t = kc*2 + s;
            uint32_t kb[2], kl2[2];
            *(uint2*)kb  = *(const uint2*)(khi + (t*32 + lane)*2);
            *(uint2*)kl2 = *(const uint2*)(klo + (t*32 + lane)*2);
            float d[4] = {0.f, 0.f, 0.f, 0.f};
            mma_bf16(d, qhi, kb);
            mma_bf16(d, qhi, kl2);
            mma_bf16(d, qlo, kb);
            float t0, t1, t2, t3;
            asm("ex2.approx.f32 %0,%1;" : "=f"(t0) : "f"(d[0]));
            asm("ex2.approx.f32 %0,%1;" : "=f"(t1) : "f"(d[1]));
            asm("ex2.approx.f32 %0,%1;" : "=f"(t2) : "f"(d[2]));
            asm("ex2.approx.f32 %0,%1;" : "=f"(t3) : "f"(d[3]));
            e[s][0] = t0 * inv0; e[s][1] = t1 * inv0;
            e[s][2] = t2 * inv1; e[s][3] = t3 * inv1;
            // coalesced-ish A stores (8B per lane, 32B/row sectors)
            *(float2*)(Ar1 + t*8) = make_float2(e[s][0], e[s][1]);
            *(float2*)(Ar2 + t*8) = make_float2(e[s][2], e[s][3]);
        }
        // repack normalized e -> A-fragment (m16 x k16), split hi/lo
        uint32_t ahi[4], alo[4];
        split2(e[0][0], e[0][1], ahi[0], alo[0]);
        split2(e[0][2], e[0][3], ahi[1], alo[1]);
        split2(e[1][0], e[1][1], ahi[2], alo[2]);
        split2(e[1][2], e[1][3], ahi[3], alo[3]);
        // AV: two d-tiles (cols 0..7, 8..15)
        {
            uint32_t vb[2], vl2[2];
            *(uint2*)vb  = *(const uint2*)(vhi + ((kc*2 + 0)*32 + lane)*2);
            *(uint2*)vl2 = *(const uint2*)(vlo + ((kc*2 + 0)*32 + lane)*2);
            mma_bf16(cA, ahi, vb);
            mma_bf16(cA, ahi, vl2);
            mma_bf16(cA, alo, vb);
        }
        {
            uint32_t vb[2], vl2[2];
            *(uint2*)vb  = *(const uint2*)(vhi + ((kc*2 + 1)*32 + lane)*2);
            *(uint2*)vl2 = *(const uint2*)(vlo + ((kc*2 + 1)*32 + lane)*2);
            mma_bf16(cB, ahi, vb);
            mma_bf16(cB, ahi, vl2);
            mma_bf16(cB, alo, vb);
        }
    }

    // ---- epilogue: Hcat (already normalized) ----
    {
        int b = bh / NH, h = bh - (bh / NH)*NH;
        float* Hp = g_Hcat + ((size_t)(b*S_ + q0 + warp*16))*DM + h*DK;
        *(float2*)(Hp + gid*DM + tg*2)           = make_float2(cA[0], cA[1]);
        *(float2*)(Hp + (gid+8)*DM + tg*2)       = make_float2(cA[2], cA[3]);
        *(float2*)(Hp + gid*DM + 8 + tg*2)       = make_float2(cB[0], cB[1]);
        *(float2*)(Hp + (gid+8)*DM + 8 + tg*2)   = make_float2(cB[2], cB[3]);
    }
}

// ---------------------------------------------------------------------------
extern "C" void kernel_launch(void* const* d_in, const int* in_sizes, int n_in,
                              void* d_out, int out_size)
{
    const float* Xq = (const float*)d_in[0];
    const float* Xk = (const float*)d_in[1];
    const float* Xv = (const float*)d_in[2];
    const float* Wq = (const float*)d_in[3];
    const float* bq = (const float*)d_in[4];
    const float* Wk = (const float*)d_in[5];
    const float* bk = (const float*)d_in[6];
    const float* Wv = (const float*)d_in[7];
    const float* bv = (const float*)d_in[8];
    const float* Wh = (const float*)d_in[9];
    const float* bh = (const float*)d_in[10];

    float* outH = (float*)d_out;
    float* outA = (float*)d_out + H_ELEMS;

    cudaFuncSetAttribute(attn_mma, cudaFuncAttributeMaxDynamicSharedMemorySize, SMEM_BYTES);

    qkv48<<<dim3(256, 3), 384>>>(Xq, Wq, bq, Xk, Wk, bk, Xv, Wv, bv);
    attn_mma<<<dim3(4, BH_), 512, SMEM_BYTES>>>(outA);
    proj48<<<256, 384>>>(Wh, bh, outH);
}